// round 2
// baseline (speedup 1.0000x reference)
#include <cuda_runtime.h>

#define NUM_CLS 32000
#define BATCH   4096
#define C4      (NUM_CLS / 4)   // 8000 float4 per row
#define THREADS 256

// Per-row partial results (deterministic two-stage reduction; no float atomics).
__device__ float g_row[BATCH];

__global__ __launch_bounds__(THREADS)
void rce_row_kernel(const float* __restrict__ inp, const float* __restrict__ tgt)
{
    const int row = blockIdx.x;
    const float4* ip = reinterpret_cast<const float4*>(inp + (size_t)row * NUM_CLS);
    const float4* tp = reinterpret_cast<const float4*>(tgt + (size_t)row * NUM_CLS);

    float s_sum = 0.f;   // sum of x
    float e_sum = 0.f;   // sum of exp(-x)
    // argmin key: (bits(value) << 32) | col  — min gives smallest value,
    // smallest column on ties (matches jnp.argmin first-occurrence).
    unsigned long long key = 0xffffffffffffffffULL;

    #pragma unroll 4
    for (int i = threadIdx.x; i < C4; i += THREADS) {
        float4 x = ip[i];
        float4 t = tp[i];

        s_sum += (x.x + x.y) + (x.z + x.w);
        e_sum += (__expf(-x.x) + __expf(-x.y)) + (__expf(-x.z) + __expf(-x.w));

        unsigned base = (unsigned)i * 4u;
        unsigned long long k0 = ((unsigned long long)__float_as_uint(t.x) << 32) | (base + 0u);
        unsigned long long k1 = ((unsigned long long)__float_as_uint(t.y) << 32) | (base + 1u);
        unsigned long long k2 = ((unsigned long long)__float_as_uint(t.z) << 32) | (base + 2u);
        unsigned long long k3 = ((unsigned long long)__float_as_uint(t.w) << 32) | (base + 3u);
        unsigned long long ka = k0 < k1 ? k0 : k1;
        unsigned long long kb = k2 < k3 ? k2 : k3;
        unsigned long long kc = ka < kb ? ka : kb;
        key = key < kc ? key : kc;
    }

    // Warp reduce
    #pragma unroll
    for (int o = 16; o > 0; o >>= 1) {
        s_sum += __shfl_xor_sync(0xffffffffu, s_sum, o);
        e_sum += __shfl_xor_sync(0xffffffffu, e_sum, o);
        unsigned long long ok = __shfl_xor_sync(0xffffffffu, key, o);
        key = key < ok ? key : ok;
    }

    __shared__ float              sh_s[THREADS / 32];
    __shared__ float              sh_e[THREADS / 32];
    __shared__ unsigned long long sh_k[THREADS / 32];
    const int wid = threadIdx.x >> 5;
    const int lid = threadIdx.x & 31;
    if (lid == 0) { sh_s[wid] = s_sum; sh_e[wid] = e_sum; sh_k[wid] = key; }
    __syncthreads();

    if (threadIdx.x == 0) {
        float S = sh_s[0], E = sh_e[0];
        unsigned long long K = sh_k[0];
        #pragma unroll
        for (int w = 1; w < THREADS / 32; w++) {
            S += sh_s[w];
            E += sh_e[w];
            K = K < sh_k[w] ? K : sh_k[w];
        }
        const int idx = (int)(K & 0xffffffffULL);
        const float xi = inp[(size_t)row * NUM_CLS + idx];
        // r_b = S_b + (C-1)*log(E_b) - x[b, idx]
        g_row[row] = S + (float)(NUM_CLS - 1) * logf(E) - xi;
    }
}

__global__ __launch_bounds__(1024)
void rce_reduce_kernel(float* __restrict__ out)
{
    float s = 0.f;
    for (int i = threadIdx.x; i < BATCH; i += 1024) s += g_row[i];

    #pragma unroll
    for (int o = 16; o > 0; o >>= 1)
        s += __shfl_xor_sync(0xffffffffu, s, o);

    __shared__ float sh[32];
    const int wid = threadIdx.x >> 5;
    const int lid = threadIdx.x & 31;
    if (lid == 0) sh[wid] = s;
    __syncthreads();

    if (threadIdx.x == 0) {
        float tot = 0.f;
        #pragma unroll
        for (int w = 0; w < 32; w++) tot += sh[w];
        // loss = (RATIO / (B * (C-1))) * sum_b r_b ;  RATIO = 1.0
        out[0] = tot * (1.0f / ((float)BATCH * (float)(NUM_CLS - 1)));
    }
}

extern "C" void kernel_launch(void* const* d_in, const int* in_sizes, int n_in,
                              void* d_out, int out_size)
{
    const float* inp = (const float*)d_in[0];   // input  [B, C] f32
    const float* tgt = (const float*)d_in[1];   // target [B, C] f32
    float* out = (float*)d_out;                 // scalar f32

    rce_row_kernel<<<BATCH, THREADS>>>(inp, tgt);
    rce_reduce_kernel<<<1, 1024>>>(out);
}